// round 6
// baseline (speedup 1.0000x reference)
#include <cuda_runtime.h>
#include <cuda_bf16.h>

// DiffJPEG per-8x8-block: D @ X @ D^T -> round(./Q)*Q -> D^T @ M @ D
// One thread per block. f32x2 packed math + even/odd butterfly decomposition.
// R6: 128-thread CTAs (finer wave stagger), double-buffered pass-1 loads,
// streaming (evict-first) loads/stores since data is single-touch.

using u64 = unsigned long long;

// D[i][j] = c_i * cos((2j+1) i pi / 16), c_0 = sqrt(1/8), else 0.5
__device__ constexpr float DMc[8][8] = {
    { 0.3535533905932738f,  0.3535533905932738f,  0.3535533905932738f,  0.3535533905932738f,
      0.3535533905932738f,  0.3535533905932738f,  0.3535533905932738f,  0.3535533905932738f },
    { 0.4903926402016152f,  0.4157348061512726f,  0.2777851165098011f,  0.0975451610080642f,
     -0.0975451610080642f, -0.2777851165098011f, -0.4157348061512726f, -0.4903926402016152f },
    { 0.4619397662556434f,  0.1913417161825449f, -0.1913417161825449f, -0.4619397662556434f,
     -0.4619397662556434f, -0.1913417161825449f,  0.1913417161825449f,  0.4619397662556434f },
    { 0.4157348061512726f, -0.0975451610080642f, -0.4903926402016152f, -0.2777851165098011f,
      0.2777851165098011f,  0.4903926402016152f,  0.0975451610080642f, -0.4157348061512726f },
    { 0.3535533905932738f, -0.3535533905932738f, -0.3535533905932738f,  0.3535533905932738f,
      0.3535533905932738f, -0.3535533905932738f, -0.3535533905932738f,  0.3535533905932738f },
    { 0.2777851165098011f, -0.4903926402016152f,  0.0975451610080642f,  0.4157348061512726f,
     -0.4157348061512726f, -0.0975451610080642f,  0.4903926402016152f, -0.2777851165098011f },
    { 0.1913417161825449f, -0.4619397662556434f,  0.4619397662556434f, -0.1913417161825449f,
     -0.1913417161825449f,  0.4619397662556434f, -0.4619397662556434f,  0.1913417161825449f },
    { 0.0975451610080642f, -0.2777851165098011f,  0.4157348061512726f, -0.4903926402016152f,
      0.4903926402016152f, -0.4157348061512726f,  0.2777851165098011f, -0.0975451610080642f },
};

// quality=50 -> Q == q_luma exactly.
__device__ constexpr float QMc[8][8] = {
    { 16.f, 11.f, 10.f, 16.f,  24.f,  40.f,  51.f,  61.f },
    { 12.f, 12.f, 14.f, 19.f,  26.f,  58.f,  60.f,  55.f },
    { 14.f, 13.f, 16.f, 24.f,  40.f,  57.f,  69.f,  56.f },
    { 14.f, 17.f, 22.f, 29.f,  51.f,  87.f,  80.f,  62.f },
    { 18.f, 22.f, 37.f, 56.f,  68.f, 109.f, 103.f,  77.f },
    { 24.f, 35.f, 55.f, 64.f,  81.f, 104.f, 113.f,  92.f },
    { 49.f, 64.f, 78.f, 87.f, 103.f, 121.f, 120.f, 101.f },
    { 72.f, 92.f, 95.f, 98.f, 112.f, 100.f, 103.f,  99.f },
};

__device__ __forceinline__ u64 pk(float a, float b) {
    u64 r; asm("mov.b64 %0, {%1, %2};" : "=l"(r) : "f"(a), "f"(b)); return r;
}
__device__ __forceinline__ void unpk(float& a, float& b, u64 v) {
    asm("mov.b64 {%0, %1}, %2;" : "=f"(a), "=f"(b) : "l"(v));
}
__device__ __forceinline__ u64 fma2(u64 a, u64 b, u64 c) {
    u64 d; asm("fma.rn.f32x2 %0, %1, %2, %3;" : "=l"(d) : "l"(a), "l"(b), "l"(c)); return d;
}
__device__ __forceinline__ u64 mul2(u64 a, u64 b) {
    u64 d; asm("mul.rn.f32x2 %0, %1, %2;" : "=l"(d) : "l"(a), "l"(b)); return d;
}
__device__ __forceinline__ u64 add2(u64 a, u64 b) {
    u64 d; asm("add.rn.f32x2 %0, %1, %2;" : "=l"(d) : "l"(a), "l"(b)); return d;
}
// a - b  (via fma with packed -1)
__device__ __forceinline__ u64 sub2(u64 a, u64 b, u64 neg1) {
    return fma2(b, neg1, a);
}

__global__ void __launch_bounds__(128, 6)
diffjpeg_kernel(const float* __restrict__ in, float* __restrict__ out, int nblk)
{
    int tid = blockIdx.x * 128 + threadIdx.x;
    if (tid >= nblk) return;

    const u64 NEG1 = pk(-1.0f, -1.0f);

    int bw  = tid & 63;           // block col (64 per row)
    int t1  = tid >> 6;
    int bh  = t1 & 63;            // block row
    int img = t1 >> 6;            // fused (B,C) plane

    size_t base = ((size_t)img << 18) + ((size_t)bh << 12) + ((size_t)bw << 3);
    const float* p = in  + base;
    float*       q = out + base;

    u64 A[8][4];   // 8 rows x 4 packed j-pairs

    // ---- pass 1: A = D @ X (column transform) via row butterfly ----------
    // Double-buffered: keep 2 butterfly-pairs of loads in flight.
    {
        u64 XT[2][4], XB[2][4];     // [slot][packed-pair]: top row t, bottom row 7-t
        #pragma unroll
        for (int s = 0; s < 2; ++s) {
            ulonglong2 ta = __ldcs(reinterpret_cast<const ulonglong2*>(p + (size_t)s * 512));
            ulonglong2 tb = __ldcs(reinterpret_cast<const ulonglong2*>(p + (size_t)s * 512) + 1);
            ulonglong2 ba = __ldcs(reinterpret_cast<const ulonglong2*>(p + (size_t)(7 - s) * 512));
            ulonglong2 bb = __ldcs(reinterpret_cast<const ulonglong2*>(p + (size_t)(7 - s) * 512) + 1);
            XT[s][0] = ta.x; XT[s][1] = ta.y; XT[s][2] = tb.x; XT[s][3] = tb.y;
            XB[s][0] = ba.x; XB[s][1] = ba.y; XB[s][2] = bb.x; XB[s][3] = bb.y;
        }
        #pragma unroll
        for (int t = 0; t < 4; ++t) {
            const int s = t & 1;
            u64 S[4], Dd[4];
            #pragma unroll
            for (int pp = 0; pp < 4; ++pp) {
                S[pp]  = add2(XT[s][pp], XB[s][pp]);
                Dd[pp] = sub2(XT[s][pp], XB[s][pp], NEG1);
            }
            // refill this slot with pair t+2 (slot regs now dead)
            if (t < 2) {
                ulonglong2 ta = __ldcs(reinterpret_cast<const ulonglong2*>(p + (size_t)(t + 2) * 512));
                ulonglong2 tb = __ldcs(reinterpret_cast<const ulonglong2*>(p + (size_t)(t + 2) * 512) + 1);
                ulonglong2 ba = __ldcs(reinterpret_cast<const ulonglong2*>(p + (size_t)(5 - t) * 512));
                ulonglong2 bb = __ldcs(reinterpret_cast<const ulonglong2*>(p + (size_t)(5 - t) * 512) + 1);
                XT[s][0] = ta.x; XT[s][1] = ta.y; XT[s][2] = tb.x; XT[s][3] = tb.y;
                XB[s][0] = ba.x; XB[s][1] = ba.y; XB[s][2] = bb.x; XB[s][3] = bb.y;
            }
            #pragma unroll
            for (int u = 0; u < 4; ++u) {
                u64 ce = pk(DMc[2*u][t],   DMc[2*u][t]);     // even rows use S
                u64 co = pk(DMc[2*u+1][t], DMc[2*u+1][t]);   // odd rows use Dd
                #pragma unroll
                for (int pp = 0; pp < 4; ++pp) {
                    if (t == 0) {
                        A[2*u][pp]   = mul2(ce, S[pp]);
                        A[2*u+1][pp] = mul2(co, Dd[pp]);
                    } else {
                        A[2*u][pp]   = fma2(ce, S[pp],  A[2*u][pp]);
                        A[2*u+1][pp] = fma2(co, Dd[pp], A[2*u+1][pp]);
                    }
                }
            }
        }
    }

    // ---- per row i: row-fwd butterfly, quantize, row-inv butterfly --------
    #pragma unroll
    for (int i = 0; i < 8; ++i) {
        float a0,a1,a2,a3,a4,a5,a6,a7;
        unpk(a0, a1, A[i][0]); unpk(a2, a3, A[i][1]);
        unpk(a4, a5, A[i][2]); unpk(a6, a7, A[i][3]);

        // sd[j] = (a[j]+a[7-j], a[j]-a[7-j])
        u64 sd[4];
        sd[0] = pk(a0 + a7, a0 - a7);
        sd[1] = pk(a1 + a6, a1 - a6);
        sd[2] = pk(a2 + a5, a2 - a5);
        sd[3] = pk(a3 + a4, a3 - a4);

        // r[t] = (dct[2t], dct[2t+1]) = sum_j sd[j] * (D[2t][j], D[2t+1][j])
        u64 r[4];
        #pragma unroll
        for (int t = 0; t < 4; ++t) {
            u64 acc = mul2(sd[0], pk(DMc[2*t][0], DMc[2*t+1][0]));
            #pragma unroll
            for (int j = 1; j < 4; ++j)
                acc = fma2(sd[j], pk(DMc[2*t][j], DMc[2*t+1][j]), acc);
            r[t] = acc;
        }

        // quantize/dequantize: packed scale, scalar rint, scalar rescale
        float m[8];
        #pragma unroll
        for (int t = 0; t < 4; ++t) {
            u64 sc = mul2(r[t], pk(1.0f / QMc[i][2*t], 1.0f / QMc[i][2*t+1]));
            float s0, s1; unpk(s0, s1, sc);
            m[2*t]   = rintf(s0) * QMc[i][2*t];
            m[2*t+1] = rintf(s1) * QMc[i][2*t+1];
        }

        // row-inv: u[c] = sum_t m[2t]*D[2t][c] ; v[c] = sum_t m[2t+1]*D[2t+1][c]
        // P[c] = u+v, P[7-c] = u-v   (c = 0..3)
        u64 U01, U23, V01, V23;
        {
            u64 be = pk(m[0], m[0]);
            U01 = mul2(be, pk(DMc[0][0], DMc[0][1]));
            U23 = mul2(be, pk(DMc[0][2], DMc[0][3]));
            u64 bo = pk(m[1], m[1]);
            V01 = mul2(bo, pk(DMc[1][0], DMc[1][1]));
            V23 = mul2(bo, pk(DMc[1][2], DMc[1][3]));
        }
        #pragma unroll
        for (int t = 1; t < 4; ++t) {
            u64 be = pk(m[2*t], m[2*t]);
            U01 = fma2(be, pk(DMc[2*t][0], DMc[2*t][1]), U01);
            U23 = fma2(be, pk(DMc[2*t][2], DMc[2*t][3]), U23);
            u64 bo = pk(m[2*t+1], m[2*t+1]);
            V01 = fma2(bo, pk(DMc[2*t+1][0], DMc[2*t+1][1]), V01);
            V23 = fma2(bo, pk(DMc[2*t+1][2], DMc[2*t+1][3]), V23);
        }
        A[i][0] = add2(U01, V01);            // (P0, P1)
        A[i][1] = add2(U23, V23);            // (P2, P3)
        u64 t76 = sub2(U01, V01, NEG1);      // (P7, P6)
        u64 t54 = sub2(U23, V23, NEG1);      // (P5, P4)
        { float x, y; unpk(x, y, t54); A[i][2] = pk(y, x); }  // (P4, P5)
        { float x, y; unpk(x, y, t76); A[i][3] = pk(y, x); }  // (P6, P7)
    }

    // ---- pass 5: out = D^T @ P (column transform) via butterfly ----------
    // out[i] = u_i + v_i, out[7-i] = u_i - v_i
    #pragma unroll
    for (int i = 0; i < 4; ++i) {
        u64 u[4], v[4];
        {
            u64 ce = pk(DMc[0][i], DMc[0][i]);
            u64 co = pk(DMc[1][i], DMc[1][i]);
            #pragma unroll
            for (int pp = 0; pp < 4; ++pp) {
                u[pp] = mul2(ce, A[0][pp]);
                v[pp] = mul2(co, A[1][pp]);
            }
        }
        #pragma unroll
        for (int t = 1; t < 4; ++t) {
            u64 ce = pk(DMc[2*t][i], DMc[2*t][i]);
            u64 co = pk(DMc[2*t+1][i], DMc[2*t+1][i]);
            #pragma unroll
            for (int pp = 0; pp < 4; ++pp) {
                u[pp] = fma2(ce, A[2*t][pp], u[pp]);
                v[pp] = fma2(co, A[2*t+1][pp], v[pp]);
            }
        }
        ulonglong2* ot = reinterpret_cast<ulonglong2*>(q + (size_t)i * 512);
        ulonglong2* ob = reinterpret_cast<ulonglong2*>(q + (size_t)(7 - i) * 512);
        __stcs(ot,     make_ulonglong2(add2(u[0], v[0]), add2(u[1], v[1])));
        __stcs(ot + 1, make_ulonglong2(add2(u[2], v[2]), add2(u[3], v[3])));
        __stcs(ob,     make_ulonglong2(sub2(u[0], v[0], NEG1), sub2(u[1], v[1], NEG1)));
        __stcs(ob + 1, make_ulonglong2(sub2(u[2], v[2], NEG1), sub2(u[3], v[3], NEG1)));
    }
}

extern "C" void kernel_launch(void* const* d_in, const int* in_sizes, int n_in,
                              void* d_out, int out_size)
{
    const float* in  = (const float*)d_in[0];
    float*       out = (float*)d_out;
    int nblk = in_sizes[0] / 64;                 // number of 8x8 blocks
    int grid = (nblk + 127) / 128;
    diffjpeg_kernel<<<grid, 128>>>(in, out, nblk);
}

// round 7
// speedup vs baseline: 1.0047x; 1.0047x over previous
#include <cuda_runtime.h>
#include <cuda_bf16.h>

// DiffJPEG per-8x8-block: D @ X @ D^T -> round(./Q)*Q -> D^T @ M @ D
// One thread per block. f32x2 packed math + even/odd butterfly decomposition.
// R6: 128-thread CTAs (finer wave stagger), double-buffered pass-1 loads,
// streaming (evict-first) loads/stores since data is single-touch.

using u64 = unsigned long long;

// D[i][j] = c_i * cos((2j+1) i pi / 16), c_0 = sqrt(1/8), else 0.5
__device__ constexpr float DMc[8][8] = {
    { 0.3535533905932738f,  0.3535533905932738f,  0.3535533905932738f,  0.3535533905932738f,
      0.3535533905932738f,  0.3535533905932738f,  0.3535533905932738f,  0.3535533905932738f },
    { 0.4903926402016152f,  0.4157348061512726f,  0.2777851165098011f,  0.0975451610080642f,
     -0.0975451610080642f, -0.2777851165098011f, -0.4157348061512726f, -0.4903926402016152f },
    { 0.4619397662556434f,  0.1913417161825449f, -0.1913417161825449f, -0.4619397662556434f,
     -0.4619397662556434f, -0.1913417161825449f,  0.1913417161825449f,  0.4619397662556434f },
    { 0.4157348061512726f, -0.0975451610080642f, -0.4903926402016152f, -0.2777851165098011f,
      0.2777851165098011f,  0.4903926402016152f,  0.0975451610080642f, -0.4157348061512726f },
    { 0.3535533905932738f, -0.3535533905932738f, -0.3535533905932738f,  0.3535533905932738f,
      0.3535533905932738f, -0.3535533905932738f, -0.3535533905932738f,  0.3535533905932738f },
    { 0.2777851165098011f, -0.4903926402016152f,  0.0975451610080642f,  0.4157348061512726f,
     -0.4157348061512726f, -0.0975451610080642f,  0.4903926402016152f, -0.2777851165098011f },
    { 0.1913417161825449f, -0.4619397662556434f,  0.4619397662556434f, -0.1913417161825449f,
     -0.1913417161825449f,  0.4619397662556434f, -0.4619397662556434f,  0.1913417161825449f },
    { 0.0975451610080642f, -0.2777851165098011f,  0.4157348061512726f, -0.4903926402016152f,
      0.4903926402016152f, -0.4157348061512726f,  0.2777851165098011f, -0.0975451610080642f },
};

// quality=50 -> Q == q_luma exactly.
__device__ constexpr float QMc[8][8] = {
    { 16.f, 11.f, 10.f, 16.f,  24.f,  40.f,  51.f,  61.f },
    { 12.f, 12.f, 14.f, 19.f,  26.f,  58.f,  60.f,  55.f },
    { 14.f, 13.f, 16.f, 24.f,  40.f,  57.f,  69.f,  56.f },
    { 14.f, 17.f, 22.f, 29.f,  51.f,  87.f,  80.f,  62.f },
    { 18.f, 22.f, 37.f, 56.f,  68.f, 109.f, 103.f,  77.f },
    { 24.f, 35.f, 55.f, 64.f,  81.f, 104.f, 113.f,  92.f },
    { 49.f, 64.f, 78.f, 87.f, 103.f, 121.f, 120.f, 101.f },
    { 72.f, 92.f, 95.f, 98.f, 112.f, 100.f, 103.f,  99.f },
};

__device__ __forceinline__ u64 pk(float a, float b) {
    u64 r; asm("mov.b64 %0, {%1, %2};" : "=l"(r) : "f"(a), "f"(b)); return r;
}
__device__ __forceinline__ void unpk(float& a, float& b, u64 v) {
    asm("mov.b64 {%0, %1}, %2;" : "=f"(a), "=f"(b) : "l"(v));
}
__device__ __forceinline__ u64 fma2(u64 a, u64 b, u64 c) {
    u64 d; asm("fma.rn.f32x2 %0, %1, %2, %3;" : "=l"(d) : "l"(a), "l"(b), "l"(c)); return d;
}
__device__ __forceinline__ u64 mul2(u64 a, u64 b) {
    u64 d; asm("mul.rn.f32x2 %0, %1, %2;" : "=l"(d) : "l"(a), "l"(b)); return d;
}
__device__ __forceinline__ u64 add2(u64 a, u64 b) {
    u64 d; asm("add.rn.f32x2 %0, %1, %2;" : "=l"(d) : "l"(a), "l"(b)); return d;
}
// a - b  (via fma with packed -1)
__device__ __forceinline__ u64 sub2(u64 a, u64 b, u64 neg1) {
    return fma2(b, neg1, a);
}

__global__ void __launch_bounds__(128, 6)
diffjpeg_kernel(const float* __restrict__ in, float* __restrict__ out, int nblk)
{
    int tid = blockIdx.x * 128 + threadIdx.x;
    if (tid >= nblk) return;

    const u64 NEG1 = pk(-1.0f, -1.0f);

    int bw  = tid & 63;           // block col (64 per row)
    int t1  = tid >> 6;
    int bh  = t1 & 63;            // block row
    int img = t1 >> 6;            // fused (B,C) plane

    size_t base = ((size_t)img << 18) + ((size_t)bh << 12) + ((size_t)bw << 3);
    const float* p = in  + base;
    float*       q = out + base;

    u64 A[8][4];   // 8 rows x 4 packed j-pairs

    // ---- pass 1: A = D @ X (column transform) via row butterfly ----------
    // Double-buffered: keep 2 butterfly-pairs of loads in flight.
    {
        u64 XT[2][4], XB[2][4];     // [slot][packed-pair]: top row t, bottom row 7-t
        #pragma unroll
        for (int s = 0; s < 2; ++s) {
            ulonglong2 ta = __ldcs(reinterpret_cast<const ulonglong2*>(p + (size_t)s * 512));
            ulonglong2 tb = __ldcs(reinterpret_cast<const ulonglong2*>(p + (size_t)s * 512) + 1);
            ulonglong2 ba = __ldcs(reinterpret_cast<const ulonglong2*>(p + (size_t)(7 - s) * 512));
            ulonglong2 bb = __ldcs(reinterpret_cast<const ulonglong2*>(p + (size_t)(7 - s) * 512) + 1);
            XT[s][0] = ta.x; XT[s][1] = ta.y; XT[s][2] = tb.x; XT[s][3] = tb.y;
            XB[s][0] = ba.x; XB[s][1] = ba.y; XB[s][2] = bb.x; XB[s][3] = bb.y;
        }
        #pragma unroll
        for (int t = 0; t < 4; ++t) {
            const int s = t & 1;
            u64 S[4], Dd[4];
            #pragma unroll
            for (int pp = 0; pp < 4; ++pp) {
                S[pp]  = add2(XT[s][pp], XB[s][pp]);
                Dd[pp] = sub2(XT[s][pp], XB[s][pp], NEG1);
            }
            // refill this slot with pair t+2 (slot regs now dead)
            if (t < 2) {
                ulonglong2 ta = __ldcs(reinterpret_cast<const ulonglong2*>(p + (size_t)(t + 2) * 512));
                ulonglong2 tb = __ldcs(reinterpret_cast<const ulonglong2*>(p + (size_t)(t + 2) * 512) + 1);
                ulonglong2 ba = __ldcs(reinterpret_cast<const ulonglong2*>(p + (size_t)(5 - t) * 512));
                ulonglong2 bb = __ldcs(reinterpret_cast<const ulonglong2*>(p + (size_t)(5 - t) * 512) + 1);
                XT[s][0] = ta.x; XT[s][1] = ta.y; XT[s][2] = tb.x; XT[s][3] = tb.y;
                XB[s][0] = ba.x; XB[s][1] = ba.y; XB[s][2] = bb.x; XB[s][3] = bb.y;
            }
            #pragma unroll
            for (int u = 0; u < 4; ++u) {
                u64 ce = pk(DMc[2*u][t],   DMc[2*u][t]);     // even rows use S
                u64 co = pk(DMc[2*u+1][t], DMc[2*u+1][t]);   // odd rows use Dd
                #pragma unroll
                for (int pp = 0; pp < 4; ++pp) {
                    if (t == 0) {
                        A[2*u][pp]   = mul2(ce, S[pp]);
                        A[2*u+1][pp] = mul2(co, Dd[pp]);
                    } else {
                        A[2*u][pp]   = fma2(ce, S[pp],  A[2*u][pp]);
                        A[2*u+1][pp] = fma2(co, Dd[pp], A[2*u+1][pp]);
                    }
                }
            }
        }
    }

    // ---- per row i: row-fwd butterfly, quantize, row-inv butterfly --------
    #pragma unroll
    for (int i = 0; i < 8; ++i) {
        float a0,a1,a2,a3,a4,a5,a6,a7;
        unpk(a0, a1, A[i][0]); unpk(a2, a3, A[i][1]);
        unpk(a4, a5, A[i][2]); unpk(a6, a7, A[i][3]);

        // sd[j] = (a[j]+a[7-j], a[j]-a[7-j])
        u64 sd[4];
        sd[0] = pk(a0 + a7, a0 - a7);
        sd[1] = pk(a1 + a6, a1 - a6);
        sd[2] = pk(a2 + a5, a2 - a5);
        sd[3] = pk(a3 + a4, a3 - a4);

        // r[t] = (dct[2t], dct[2t+1]) = sum_j sd[j] * (D[2t][j], D[2t+1][j])
        u64 r[4];
        #pragma unroll
        for (int t = 0; t < 4; ++t) {
            u64 acc = mul2(sd[0], pk(DMc[2*t][0], DMc[2*t+1][0]));
            #pragma unroll
            for (int j = 1; j < 4; ++j)
                acc = fma2(sd[j], pk(DMc[2*t][j], DMc[2*t+1][j]), acc);
            r[t] = acc;
        }

        // quantize/dequantize: packed scale, scalar rint, scalar rescale
        float m[8];
        #pragma unroll
        for (int t = 0; t < 4; ++t) {
            u64 sc = mul2(r[t], pk(1.0f / QMc[i][2*t], 1.0f / QMc[i][2*t+1]));
            float s0, s1; unpk(s0, s1, sc);
            m[2*t]   = rintf(s0) * QMc[i][2*t];
            m[2*t+1] = rintf(s1) * QMc[i][2*t+1];
        }

        // row-inv: u[c] = sum_t m[2t]*D[2t][c] ; v[c] = sum_t m[2t+1]*D[2t+1][c]
        // P[c] = u+v, P[7-c] = u-v   (c = 0..3)
        u64 U01, U23, V01, V23;
        {
            u64 be = pk(m[0], m[0]);
            U01 = mul2(be, pk(DMc[0][0], DMc[0][1]));
            U23 = mul2(be, pk(DMc[0][2], DMc[0][3]));
            u64 bo = pk(m[1], m[1]);
            V01 = mul2(bo, pk(DMc[1][0], DMc[1][1]));
            V23 = mul2(bo, pk(DMc[1][2], DMc[1][3]));
        }
        #pragma unroll
        for (int t = 1; t < 4; ++t) {
            u64 be = pk(m[2*t], m[2*t]);
            U01 = fma2(be, pk(DMc[2*t][0], DMc[2*t][1]), U01);
            U23 = fma2(be, pk(DMc[2*t][2], DMc[2*t][3]), U23);
            u64 bo = pk(m[2*t+1], m[2*t+1]);
            V01 = fma2(bo, pk(DMc[2*t+1][0], DMc[2*t+1][1]), V01);
            V23 = fma2(bo, pk(DMc[2*t+1][2], DMc[2*t+1][3]), V23);
        }
        A[i][0] = add2(U01, V01);            // (P0, P1)
        A[i][1] = add2(U23, V23);            // (P2, P3)
        u64 t76 = sub2(U01, V01, NEG1);      // (P7, P6)
        u64 t54 = sub2(U23, V23, NEG1);      // (P5, P4)
        { float x, y; unpk(x, y, t54); A[i][2] = pk(y, x); }  // (P4, P5)
        { float x, y; unpk(x, y, t76); A[i][3] = pk(y, x); }  // (P6, P7)
    }

    // ---- pass 5: out = D^T @ P (column transform) via butterfly ----------
    // out[i] = u_i + v_i, out[7-i] = u_i - v_i
    #pragma unroll
    for (int i = 0; i < 4; ++i) {
        u64 u[4], v[4];
        {
            u64 ce = pk(DMc[0][i], DMc[0][i]);
            u64 co = pk(DMc[1][i], DMc[1][i]);
            #pragma unroll
            for (int pp = 0; pp < 4; ++pp) {
                u[pp] = mul2(ce, A[0][pp]);
                v[pp] = mul2(co, A[1][pp]);
            }
        }
        #pragma unroll
        for (int t = 1; t < 4; ++t) {
            u64 ce = pk(DMc[2*t][i], DMc[2*t][i]);
            u64 co = pk(DMc[2*t+1][i], DMc[2*t+1][i]);
            #pragma unroll
            for (int pp = 0; pp < 4; ++pp) {
                u[pp] = fma2(ce, A[2*t][pp], u[pp]);
                v[pp] = fma2(co, A[2*t+1][pp], v[pp]);
            }
        }
        ulonglong2* ot = reinterpret_cast<ulonglong2*>(q + (size_t)i * 512);
        ulonglong2* ob = reinterpret_cast<ulonglong2*>(q + (size_t)(7 - i) * 512);
        __stcs(ot,     make_ulonglong2(add2(u[0], v[0]), add2(u[1], v[1])));
        __stcs(ot + 1, make_ulonglong2(add2(u[2], v[2]), add2(u[3], v[3])));
        __stcs(ob,     make_ulonglong2(sub2(u[0], v[0], NEG1), sub2(u[1], v[1], NEG1)));
        __stcs(ob + 1, make_ulonglong2(sub2(u[2], v[2], NEG1), sub2(u[3], v[3], NEG1)));
    }
}

extern "C" void kernel_launch(void* const* d_in, const int* in_sizes, int n_in,
                              void* d_out, int out_size)
{
    const float* in  = (const float*)d_in[0];
    float*       out = (float*)d_out;
    int nblk = in_sizes[0] / 64;                 // number of 8x8 blocks
    int grid = (nblk + 127) / 128;
    diffjpeg_kernel<<<grid, 128>>>(in, out, nblk);
}